// round 1
// baseline (speedup 1.0000x reference)
#include <cuda_runtime.h>
#include <cstdint>

#define FULL 0xffffffffu

// Problem constants
#define B_  8
#define L_  128
#define D_  512
#define H_  8
#define DV_ 64

// d_out layout: [final (B*L*D) | attn_value (B*H*L*L) | attn_relation (B*H*L*L)]
#define AV_OFF  (B_*L_*D_)            // 524288
#define AR_OFF  (AV_OFF + B_*H_*L_*L_) // 1572864

// ---------------- device scratch (no allocs allowed) ----------------
__device__ __align__(16) float g_value[B_*H_*L_*DV_];     // (b,h,l,dv)  2MB
__device__ float g_esrc[B_*H_*L_];
__device__ float g_etgt[B_*H_*L_];
__device__ __align__(16) unsigned long long g_wrp[256*8]; // paired Wr_eff
__device__ __align__(16) float g_concat[B_*L_*2*D_];      // 4MB

// ---------------- f32x2 packed FMA (sm_100+) ----------------
__device__ __forceinline__ unsigned long long ffma2(unsigned long long a,
                                                    unsigned long long b,
                                                    unsigned long long c) {
    unsigned long long d;
    asm("fma.rn.f32x2 %0, %1, %2, %3;" : "=l"(d) : "l"(a), "l"(b), "l"(c));
    return d;
}
__device__ __forceinline__ float pairsum(unsigned long long v) {
    float2 f = *reinterpret_cast<float2*>(&v);
    return f.x + f.y;
}

// ---------------- Wr_eff[k][h] = sum_d W_relation[k][h*64+d]*w_rel[h][d] ----------------
__global__ void k_wr(const float* __restrict__ Wrel, const float* __restrict__ wrel) {
    int gw = blockIdx.x * 8 + (threadIdx.x >> 5);   // 0..4095  => (k,h)
    int lane = threadIdx.x & 31;
    int k = gw >> 3, h = gw & 7;
    const float* r = Wrel + (size_t)k * 512 + h * 64;
    const float* w = wrel + h * 64;
    float s = r[lane] * w[lane] + r[lane + 32] * w[lane + 32];
    #pragma unroll
    for (int o = 16; o; o >>= 1) s += __shfl_xor_sync(FULL, s, o);
    if (lane == 0)
        ((float*)g_wrp)[(k >> 1) * 16 + h * 2 + (k & 1)] = s;  // pair layout
}

// ---------------- 64x64x16 f32x2 register-tiled GEMM ----------------
// EPI==1: value GEMM epilogue -> g_value in (b,h,l,dv) layout
// EPI==2: final GEMM: A is g_concat (ignored param), C = A@B + bias + resid
template<int EPI>
__global__ void gemm64(const float* __restrict__ A, const float* __restrict__ Bm,
                       float* __restrict__ C, int K, int N,
                       const float* __restrict__ bias, const float* __restrict__ resid) {
    __shared__ float As[64][18];
    __shared__ float Bs[64][18];   // transposed: Bs[n][k]
    if (EPI == 2) A = g_concat;
    int t = threadIdx.x;
    int tx = t & 15, ty = t >> 4;
    int row0 = blockIdx.y << 6, col0 = blockIdx.x << 6;
    unsigned long long acc[4][4];
    #pragma unroll
    for (int m = 0; m < 4; m++)
        #pragma unroll
        for (int n = 0; n < 4; n++) acc[m][n] = 0ull;
    int ar = t >> 2, ac = (t & 3) << 2;
    int br = t >> 4, bc = (t & 15) << 2;
    for (int k0 = 0; k0 < K; k0 += 16) {
        float4 av = *(const float4*)(A + (size_t)(row0 + ar) * K + k0 + ac);
        float4 bv = *(const float4*)(Bm + (size_t)(k0 + br) * N + col0 + bc);
        As[ar][ac + 0] = av.x; As[ar][ac + 1] = av.y; As[ar][ac + 2] = av.z; As[ar][ac + 3] = av.w;
        Bs[bc + 0][br] = bv.x; Bs[bc + 1][br] = bv.y; Bs[bc + 2][br] = bv.z; Bs[bc + 3][br] = bv.w;
        __syncthreads();
        #pragma unroll
        for (int p = 0; p < 8; p++) {
            unsigned long long a2[4], b2[4];
            #pragma unroll
            for (int m = 0; m < 4; m++) a2[m] = *(unsigned long long*)&As[(ty << 2) + m][p << 1];
            #pragma unroll
            for (int n = 0; n < 4; n++) b2[n] = *(unsigned long long*)&Bs[(tx << 2) + n][p << 1];
            #pragma unroll
            for (int m = 0; m < 4; m++)
                #pragma unroll
                for (int n = 0; n < 4; n++)
                    acc[m][n] = ffma2(a2[m], b2[n], acc[m][n]);
        }
        __syncthreads();
    }
    #pragma unroll
    for (int m = 0; m < 4; m++) {
        int row = row0 + (ty << 2) + m;
        #pragma unroll
        for (int n = 0; n < 4; n++) {
            int col = col0 + (tx << 2) + n;
            float v = pairsum(acc[m][n]);
            if (EPI == 1) {
                int b = row >> 7, l = row & 127, h = col >> 6, dv = col & 63;
                g_value[(size_t)((((b << 3) | h) << 7) | l) * 64 + dv] = v;
            } else {
                C[(size_t)row * N + col] = v + bias[col] + resid[(size_t)row * N + col];
            }
        }
    }
}

// ---------------- e_src/e_tgt: warp per (b,h,l) ----------------
__global__ void k_e(const float* __restrict__ wsrc, const float* __restrict__ wtgt) {
    int gw = blockIdx.x * 8 + (threadIdx.x >> 5);   // 0..8191 = (b,h,l)
    int lane = threadIdx.x & 31;
    int h = (gw >> 7) & 7;
    const float* vr = g_value + (size_t)gw * 64;
    float v0 = vr[lane], v1 = vr[lane + 32];
    float ss = v0 * wsrc[h * 64 + lane] + v1 * wsrc[h * 64 + lane + 32];
    float st = v0 * wtgt[h * 64 + lane] + v1 * wtgt[h * 64 + lane + 32];
    #pragma unroll
    for (int o = 16; o; o >>= 1) {
        ss += __shfl_xor_sync(FULL, ss, o);
        st += __shfl_xor_sync(FULL, st, o);
    }
    if (lane == 0) { g_esrc[gw] = ss; g_etgt[gw] = st; }
}

// ---------------- big fused kernel: block = (b,i) ----------------
// streams relation_inp rows (b,i,j,:) for all j, computes scores_relation
// via Wr_eff, builds scores_value from e_src/e_tgt, masks, softmax+renorm,
// writes attn_value & attn_relation directly into d_out.
__global__ __launch_bounds__(128, 4)
void k_big(const float* __restrict__ rel, const int* __restrict__ adj,
           const unsigned char* __restrict__ mask, float* __restrict__ out) {
    __shared__ float As[128][34];                    // 128 j-rows x 32 k
    __shared__ unsigned long long Ws[2048];          // Wr_eff pairs [256][8]
    __shared__ float sc[2][8][132];                  // [value|rel][h][j]
    __shared__ unsigned char badf[8][128];
    int t = threadIdx.x;
    int bi = blockIdx.x;                             // b*128 + i
    int b = bi >> 7, i = bi & 127;

    for (int idx = t; idx < 2048; idx += 128) Ws[idx] = g_wrp[idx];

    unsigned long long acc[8] = {};
    const float* base = rel + (size_t)bi * (128 * 512);
    for (int c = 0; c < 16; c++) {
        __syncthreads();
        #pragma unroll
        for (int q = 0; q < 8; q++) {
            int fi = (q << 7) + t;
            int row = fi >> 3, c4 = (fi & 7) << 2;
            float4 v = *(const float4*)(base + (size_t)row * 512 + (c << 5) + c4);
            As[row][c4 + 0] = v.x; As[row][c4 + 1] = v.y;
            As[row][c4 + 2] = v.z; As[row][c4 + 3] = v.w;
        }
        __syncthreads();
        const unsigned long long* ar = (const unsigned long long*)&As[t][0];
        const unsigned long long* wb = &Ws[(c << 4) * 8];
        #pragma unroll
        for (int p = 0; p < 16; p++) {
            unsigned long long a2 = ar[p];
            #pragma unroll
            for (int h = 0; h < 8; h++)
                acc[h] = ffma2(a2, wb[p * 8 + h], acc[h]);
        }
    }

    int j = t;
    #pragma unroll
    for (int h = 0; h < 8; h++) {
        float x = pairsum(acc[h]);
        x = x >= 0.f ? x : 0.2f * x;                                   // leaky
        float ev = g_etgt[((b << 3) + h) * 128 + i] + g_esrc[((b << 3) + h) * 128 + j];
        ev = ev >= 0.f ? ev : 0.2f * ev;
        int a = adj[(size_t)(((b << 3) + h) * 128 + i) * 128 + j];
        bool bad = (mask[(size_t)bi * 128 + j] != 0) || (a == 0);
        badf[h][j] = bad ? 1 : 0;
        sc[0][h][j] = bad ? -1e12f : ev;
        sc[1][h][j] = bad ? -1e12f : x;
    }
    __syncthreads();

    int w = t >> 5, lane = t & 31;
    #pragma unroll
    for (int hh = 0; hh < 2; hh++) {
        int h = w + (hh << 2);
        #pragma unroll
        for (int sidx = 0; sidx < 2; sidx++) {
            float x0 = sc[sidx][h][lane +  0], x1 = sc[sidx][h][lane + 32];
            float x2 = sc[sidx][h][lane + 64], x3 = sc[sidx][h][lane + 96];
            float m = fmaxf(fmaxf(x0, x1), fmaxf(x2, x3));
            #pragma unroll
            for (int o = 16; o; o >>= 1) m = fmaxf(m, __shfl_xor_sync(FULL, m, o));
            float e0 = expf(x0 - m), e1 = expf(x1 - m);
            float e2 = expf(x2 - m), e3 = expf(x3 - m);
            float Z = e0 + e1 + e2 + e3;
            #pragma unroll
            for (int o = 16; o; o >>= 1) Z += __shfl_xor_sync(FULL, Z, o);
            float inv = 1.0f / Z;
            float p0 = e0 * inv, p1 = e1 * inv, p2 = e2 * inv, p3 = e3 * inv;
            float s = p0 + p1 + p2 + p3;
            #pragma unroll
            for (int o = 16; o; o >>= 1) s += __shfl_xor_sync(FULL, s, o);
            float rinv = 1.0f / fmaxf(s, 1e-12f);
            p0 *= rinv; p1 *= rinv; p2 *= rinv; p3 *= rinv;
            if (badf[h][lane +  0]) p0 = 0.f;
            if (badf[h][lane + 32]) p1 = 0.f;
            if (badf[h][lane + 64]) p2 = 0.f;
            if (badf[h][lane + 96]) p3 = 0.f;
            size_t ob = (size_t)(sidx == 0 ? AV_OFF : AR_OFF)
                      + (size_t)(((b << 3) + h) * 128 + i) * 128;
            out[ob + lane +  0] = p0; out[ob + lane + 32] = p1;
            out[ob + lane + 64] = p2; out[ob + lane + 96] = p3;
        }
    }
}

// ---------------- out_v/out_r: block = (b,h,which) ----------------
// O[i][d] = sum_j attn[i][j] * V[j][d] ; writes into g_concat columns
__global__ void k_outvr(const float* __restrict__ out) {
    __shared__ float As[128][33];
    __shared__ __align__(16) float Vs[32][68];
    int t = threadIdx.x;
    int s = blockIdx.x & 1;
    int bh = blockIdx.x >> 1;                        // b*8+h
    const float* attn = out + (s == 0 ? AV_OFF : AR_OFF) + (size_t)bh * 128 * 128;
    const float* V = g_value + (size_t)bh * 128 * 64;
    int tx = t & 15, ty = t >> 4;
    float acc[8][4];
    #pragma unroll
    for (int mu = 0; mu < 8; mu++)
        #pragma unroll
        for (int nu = 0; nu < 4; nu++) acc[mu][nu] = 0.f;

    for (int kc = 0; kc < 128; kc += 32) {
        __syncthreads();
        #pragma unroll
        for (int q = 0; q < 4; q++) {                // 128x32 attn chunk
            int fi = (q << 8) + t;
            int row = fi >> 3, c4 = (fi & 7) << 2;
            float4 v = *(const float4*)(attn + (size_t)row * 128 + kc + c4);
            As[row][c4 + 0] = v.x; As[row][c4 + 1] = v.y;
            As[row][c4 + 2] = v.z; As[row][c4 + 3] = v.w;
        }
        #pragma unroll
        for (int q = 0; q < 2; q++) {                // 32x64 V chunk
            int fi = (q << 8) + t;
            int row = fi >> 4, c4 = (fi & 15) << 2;
            float4 v = *(const float4*)(V + (size_t)(kc + row) * 64 + c4);
            Vs[row][c4 + 0] = v.x; Vs[row][c4 + 1] = v.y;
            Vs[row][c4 + 2] = v.z; Vs[row][c4 + 3] = v.w;
        }
        __syncthreads();
        #pragma unroll
        for (int kk = 0; kk < 32; kk++) {
            float4 bv = *(const float4*)&Vs[kk][tx << 2];
            #pragma unroll
            for (int mu = 0; mu < 8; mu++) {
                float a = As[(ty << 3) + mu][kk];
                acc[mu][0] += a * bv.x; acc[mu][1] += a * bv.y;
                acc[mu][2] += a * bv.z; acc[mu][3] += a * bv.w;
            }
        }
    }
    int b = bh >> 3, h = bh & 7;
    #pragma unroll
    for (int mu = 0; mu < 8; mu++) {
        int i = (ty << 3) + mu;
        float4 v = make_float4(acc[mu][0], acc[mu][1], acc[mu][2], acc[mu][3]);
        *(float4*)(g_concat + (size_t)(b * 128 + i) * 1024 + s * 512 + h * 64 + (tx << 2)) = v;
    }
}

// ---------------- launch ----------------
extern "C" void kernel_launch(void* const* d_in, const int* in_sizes, int n_in,
                              void* d_out, int out_size) {
    const float* inp     = (const float*)d_in[0];
    const float* relin   = (const float*)d_in[1];
    const unsigned char* mask = (const unsigned char*)d_in[2];
    const int*   adj     = (const int*)d_in[3];
    // d_in[4..6]: rel_pos_mat / deprel_mat / deparc_mat — unused by reference
    const float* W_value = (const float*)d_in[7];
    const float* W_rel   = (const float*)d_in[8];
    const float* w_src   = (const float*)d_in[9];
    const float* w_tgt   = (const float*)d_in[10];
    const float* w_rel   = (const float*)d_in[11];
    const float* W_final = (const float*)d_in[12];
    const float* b_final = (const float*)d_in[13];
    float* out = (float*)d_out;

    k_wr<<<512, 256>>>(W_rel, w_rel);                                  // Wr_eff
    gemm64<1><<<dim3(8, 16), 256>>>(inp, W_value, nullptr, 512, 512,
                                    nullptr, nullptr);                 // value
    k_e<<<1024, 256>>>(w_src, w_tgt);                                  // e_src/e_tgt
    k_big<<<1024, 128>>>(relin, adj, mask, out);                       // scores+softmax+attn
    k_outvr<<<128, 256>>>(out);                                        // out_v/out_r -> concat
    gemm64<2><<<dim3(8, 16), 256>>>(nullptr, W_final, out, 1024, 512,
                                    b_final, inp);                     // final + bias + resid
}

// round 2
// speedup vs baseline: 1.3744x; 1.3744x over previous
#include <cuda_runtime.h>
#include <cstdint>

#define FULL 0xffffffffu

#define B_  8
#define L_  128
#define D_  512
#define H_  8
#define DV_ 64

// d_out layout: [final (B*L*D) | attn_value (B*H*L*L) | attn_relation (B*H*L*L)]
#define AV_OFF  (B_*L_*D_)             // 524288
#define AR_OFF  (AV_OFF + B_*H_*L_*L_) // 1572864

// ---------------- device scratch ----------------
__device__ __align__(16) float g_value[B_*H_*L_*DV_];      // (b,h,l,dv)
__device__ float g_esrc[B_*H_*L_];
__device__ float g_etgt[B_*H_*L_];
__device__ __align__(16) unsigned long long g_wrp[256*8];  // Wr_eff pairs [kp][h]
__device__ __align__(16) float g_concat[B_*L_*2*D_];       // 4MB

// ---------------- helpers ----------------
__device__ __forceinline__ unsigned long long ffma2(unsigned long long a,
                                                    unsigned long long b,
                                                    unsigned long long c) {
    unsigned long long d;
    asm("fma.rn.f32x2 %0, %1, %2, %3;" : "=l"(d) : "l"(a), "l"(b), "l"(c));
    return d;
}
__device__ __forceinline__ float pairsum(unsigned long long v) {
    float2 f = *reinterpret_cast<float2*>(&v);
    return f.x + f.y;
}
__device__ __forceinline__ uint32_t saddr(const void* p) {
    return (uint32_t)__cvta_generic_to_shared(p);
}
__device__ __forceinline__ void cp8(uint32_t dst, const void* src) {
    asm volatile("cp.async.ca.shared.global [%0], [%1], 8;" :: "r"(dst), "l"(src));
}
__device__ __forceinline__ void cp_commit() {
    asm volatile("cp.async.commit_group;");
}
template<int N> __device__ __forceinline__ void cp_wait() {
    asm volatile("cp.async.wait_group %0;" :: "n"(N));
}

// ---------------- Wr_eff[k][h] ----------------
__global__ void k_wr(const float* __restrict__ Wrel, const float* __restrict__ wrel) {
    int gw = blockIdx.x * 8 + (threadIdx.x >> 5);   // (k,h)
    int lane = threadIdx.x & 31;
    int k = gw >> 3, h = gw & 7;
    const float* r = Wrel + (size_t)k * 512 + h * 64;
    const float* w = wrel + h * 64;
    float s = r[lane] * w[lane] + r[lane + 32] * w[lane + 32];
    #pragma unroll
    for (int o = 16; o; o >>= 1) s += __shfl_xor_sync(FULL, s, o);
    if (lane == 0)
        ((float*)g_wrp)[(k >> 1) * 16 + h * 2 + (k & 1)] = s;
}

// ---------------- unified pipelined 64x64 GEMM ----------------
// EPI=1: value GEMM (A=inp[1024,512], B=W_value[512,512]) -> g_value + fused e_src/e_tgt
// EPI=2: final GEMM (A=g_concat[1024,1024], B=W_final[1024,512]) -> out + bias + resid
// EPI=3: out_v/out_r (A=attn slice[64,128], B=g_value slice[128,64]) -> g_concat
template<int EPI>
__global__ __launch_bounds__(256, 2)
void k_gemm(const float* __restrict__ A, const float* __restrict__ Bm,
            float* __restrict__ C, int K,
            const float* __restrict__ bias, const float* __restrict__ resid,
            const float* __restrict__ wsrc, const float* __restrict__ wtgt) {
    __shared__ unsigned long long Ap[2][64][9];
    __shared__ unsigned long long Bp[2][64][9];
    __shared__ float ered[2][64][17];

    int t = threadIdx.x;
    int tx = t & 15, ty = t >> 4;

    const float* Aptr; const float* Bptr;
    int lda, ldb, row0 = 0, col0 = 0;
    int s3 = 0, bh3 = 0, ihalf3 = 0;
    if (EPI == 3) {
        int bx = blockIdx.x;
        s3 = bx & 1; ihalf3 = (bx >> 1) & 1; bh3 = bx >> 2;      // b*8+h
        Aptr = C + (s3 ? AR_OFF : AV_OFF) + (size_t)bh3 * 16384 + (size_t)ihalf3 * 64 * 128;
        Bptr = g_value + (size_t)bh3 * 8192;
        lda = 128; ldb = 64;
    } else {
        col0 = blockIdx.x << 6; row0 = blockIdx.y << 6;
        Aptr = (EPI == 2) ? g_concat : A;
        Bptr = Bm;
        lda = (EPI == 2) ? 1024 : 512;
        ldb = 512;
        Aptr += (size_t)row0 * lda;
        Bptr += col0;
    }

    unsigned long long acc[4][4];
    #pragma unroll
    for (int m = 0; m < 4; m++)
        #pragma unroll
        for (int n = 0; n < 4; n++) acc[m][n] = 0ull;

    int W = K >> 4;
    int bk = t >> 4, bn0 = (t & 15) << 2;   // B stage mapping

    // prefetch B window 0 + stage A window 0
    float4 vB = *(const float4*)(Bptr + (size_t)bk * ldb + bn0);
    #pragma unroll
    for (int q = 0; q < 2; q++) {
        int fi = (q << 8) + t, row = fi >> 3, pc = fi & 7;
        cp8(saddr(&Ap[0][row][pc]), Aptr + (size_t)row * lda + (pc << 1));
    }
    cp_commit();

    for (int w = 0; w < W; w++) {
        int buf = w & 1;
        // store B(w) into shared (transposed pairs)
        ((float*)&Bp[buf][bn0 + 0][bk >> 1])[bk & 1] = vB.x;
        ((float*)&Bp[buf][bn0 + 1][bk >> 1])[bk & 1] = vB.y;
        ((float*)&Bp[buf][bn0 + 2][bk >> 1])[bk & 1] = vB.z;
        ((float*)&Bp[buf][bn0 + 3][bk >> 1])[bk & 1] = vB.w;
        if (w < W - 1) {
            vB = *(const float4*)(Bptr + (size_t)(((w + 1) << 4) + bk) * ldb + bn0);
            #pragma unroll
            for (int q = 0; q < 2; q++) {
                int fi = (q << 8) + t, row = fi >> 3, pc = fi & 7;
                cp8(saddr(&Ap[buf ^ 1][row][pc]),
                    Aptr + (size_t)row * lda + ((w + 1) << 4) + (pc << 1));
            }
            cp_commit();
            cp_wait<1>();
        } else {
            cp_wait<0>();
        }
        __syncthreads();
        #pragma unroll
        for (int p = 0; p < 8; p++) {
            unsigned long long a2[4], b2[4];
            #pragma unroll
            for (int m = 0; m < 4; m++) a2[m] = Ap[buf][ty + (m << 4)][p];
            #pragma unroll
            for (int n = 0; n < 4; n++) b2[n] = Bp[buf][tx + (n << 4)][p];
            #pragma unroll
            for (int m = 0; m < 4; m++)
                #pragma unroll
                for (int n = 0; n < 4; n++)
                    acc[m][n] = ffma2(a2[m], b2[n], acc[m][n]);
        }
        __syncthreads();
    }

    float v[4][4];
    #pragma unroll
    for (int m = 0; m < 4; m++)
        #pragma unroll
        for (int n = 0; n < 4; n++) v[m][n] = pairsum(acc[m][n]);

    if (EPI == 1) {
        int h = col0 >> 6;
        float ps[4] = {0,0,0,0}, pt[4] = {0,0,0,0};
        #pragma unroll
        for (int n = 0; n < 4; n++) {
            int dv = tx + (n << 4);
            float ws = wsrc[h * 64 + dv], wt = wtgt[h * 64 + dv];
            #pragma unroll
            for (int m = 0; m < 4; m++) {
                int rg = row0 + ty + (m << 4);
                int b = rg >> 7, l = rg & 127;
                g_value[(size_t)((((b << 3) | h) << 7) | l) * 64 + dv] = v[m][n];
                ps[m] += v[m][n] * ws;
                pt[m] += v[m][n] * wt;
            }
        }
        #pragma unroll
        for (int m = 0; m < 4; m++) {
            ered[0][ty + (m << 4)][tx] = ps[m];
            ered[1][ty + (m << 4)][tx] = pt[m];
        }
        __syncthreads();
        if (t < 128) {
            int row = t & 63, sel = t >> 6;
            float s = 0.f;
            #pragma unroll
            for (int x = 0; x < 16; x++) s += ered[sel][row][x];
            int rg = row0 + row, b = rg >> 7, l = rg & 127;
            (sel ? g_etgt : g_esrc)[((b << 3) + h) * 128 + l] = s;
        }
    } else if (EPI == 2) {
        #pragma unroll
        for (int m = 0; m < 4; m++) {
            int rg = row0 + ty + (m << 4);
            #pragma unroll
            for (int n = 0; n < 4; n++) {
                int col = col0 + tx + (n << 4);
                C[(size_t)rg * 512 + col] = v[m][n] + bias[col] + resid[(size_t)rg * 512 + col];
            }
        }
    } else {
        int b = bh3 >> 3, h = bh3 & 7;
        #pragma unroll
        for (int m = 0; m < 4; m++) {
            int ig = (ihalf3 << 6) + ty + (m << 4);
            #pragma unroll
            for (int n = 0; n < 4; n++) {
                int dv = tx + (n << 4);
                g_concat[(size_t)(b * 128 + ig) * 1024 + s3 * 512 + h * 64 + dv] = v[m][n];
            }
        }
    }
}

// ---------------- big fused kernel: block = (b,i), 256 threads ----------------
__global__ __launch_bounds__(256, 4)
void k_big(const float* __restrict__ rel, const int* __restrict__ adj,
           const unsigned char* __restrict__ mask, float* __restrict__ out) {
    __shared__ unsigned long long Asp[2][128][17];
    __shared__ float red[128][9];
    __shared__ float scr[8][132];

    int t = threadIdx.x;
    int bi = blockIdx.x, b = bi >> 7, i = bi & 127;
    const float* base = rel + (size_t)bi * 65536;

    int kh = t >> 7, ht = (t >> 5) & 3, jt = t & 31;
    int h0 = ht << 1;
    unsigned long long acc[4][2] = {};

    // stage window 0
    #pragma unroll
    for (int q = 0; q < 8; q++) {
        int fi = (q << 8) + t, row = fi >> 4, pc = fi & 15;
        cp8(saddr(&Asp[0][row][pc]), base + (size_t)row * 512 + (pc << 1));
    }
    cp_commit();

    for (int w = 0; w < 16; w++) {
        int buf = w & 1;
        if (w < 15) {
            #pragma unroll
            for (int q = 0; q < 8; q++) {
                int fi = (q << 8) + t, row = fi >> 4, pc = fi & 15;
                cp8(saddr(&Asp[buf ^ 1][row][pc]),
                    base + (size_t)row * 512 + ((w + 1) << 5) + (pc << 1));
            }
            cp_commit();
            cp_wait<1>();
        } else {
            cp_wait<0>();
        }
        __syncthreads();
        const unsigned long long* wr = g_wrp + (((w << 4) + (kh << 3)) << 3) + h0;
        #pragma unroll
        for (int p = 0; p < 8; p++) {
            ulonglong2 w2 = *(const ulonglong2*)(wr + (p << 3));
            int pp = (kh << 3) + p;
            unsigned long long a0 = Asp[buf][jt     ][pp];
            unsigned long long a1 = Asp[buf][jt + 32][pp];
            unsigned long long a2_ = Asp[buf][jt + 64][pp];
            unsigned long long a3 = Asp[buf][jt + 96][pp];
            acc[0][0] = ffma2(a0, w2.x, acc[0][0]); acc[0][1] = ffma2(a0, w2.y, acc[0][1]);
            acc[1][0] = ffma2(a1, w2.x, acc[1][0]); acc[1][1] = ffma2(a1, w2.y, acc[1][1]);
            acc[2][0] = ffma2(a2_, w2.x, acc[2][0]); acc[2][1] = ffma2(a2_, w2.y, acc[2][1]);
            acc[3][0] = ffma2(a3, w2.x, acc[3][0]); acc[3][1] = ffma2(a3, w2.y, acc[3][1]);
        }
        __syncthreads();
    }

    // k-split reduction + leaky -> scr[h][j]
    int r = (ht << 5) + jt;
    if (kh == 1) {
        #pragma unroll
        for (int m = 0; m < 4; m++)
            #pragma unroll
            for (int n = 0; n < 2; n++)
                red[r][m * 2 + n] = pairsum(acc[m][n]);
    }
    __syncthreads();
    if (kh == 0) {
        #pragma unroll
        for (int m = 0; m < 4; m++)
            #pragma unroll
            for (int n = 0; n < 2; n++) {
                float x = pairsum(acc[m][n]) + red[r][m * 2 + n];
                x = x >= 0.f ? x : 0.2f * x;
                scr[h0 + n][jt + (m << 5)] = x;
            }
    }
    __syncthreads();

    // softmax phase: warp = head
    int h = t >> 5, lane = t & 31;
    const float* esrc = g_esrc + ((b << 3) + h) * 128;
    float et = g_etgt[((b << 3) + h) * 128 + i];
    const int* adjrow = adj + ((size_t)(((b << 3) + h) * 128 + i) << 7);
    float xv[4], xr[4];
    bool bad[4];
    #pragma unroll
    for (int m = 0; m < 4; m++) {
        int j = lane + (m << 5);
        bool bd = (mask[(bi << 7) + j] != 0) || (adjrow[j] == 0);
        bad[m] = bd;
        float ev = et + esrc[j];
        ev = ev >= 0.f ? ev : 0.2f * ev;
        xv[m] = bd ? -1e12f : ev;
        xr[m] = bd ? -1e12f : scr[h][j];
    }

    auto softmax_store = [&](float x0, float x1, float x2, float x3, size_t ob) {
        float mx = fmaxf(fmaxf(x0, x1), fmaxf(x2, x3));
        #pragma unroll
        for (int o = 16; o; o >>= 1) mx = fmaxf(mx, __shfl_xor_sync(FULL, mx, o));
        float e0 = expf(x0 - mx), e1 = expf(x1 - mx);
        float e2 = expf(x2 - mx), e3 = expf(x3 - mx);
        float Z = e0 + e1 + e2 + e3;
        #pragma unroll
        for (int o = 16; o; o >>= 1) Z += __shfl_xor_sync(FULL, Z, o);
        float inv = 1.0f / Z;
        float p0 = e0 * inv, p1 = e1 * inv, p2 = e2 * inv, p3 = e3 * inv;
        float s = p0 + p1 + p2 + p3;
        #pragma unroll
        for (int o = 16; o; o >>= 1) s += __shfl_xor_sync(FULL, s, o);
        float rinv = 1.0f / fmaxf(s, 1e-12f);
        p0 *= rinv; p1 *= rinv; p2 *= rinv; p3 *= rinv;
        if (bad[0]) p0 = 0.f;
        if (bad[1]) p1 = 0.f;
        if (bad[2]) p2 = 0.f;
        if (bad[3]) p3 = 0.f;
        out[ob + lane +  0] = p0; out[ob + lane + 32] = p1;
        out[ob + lane + 64] = p2; out[ob + lane + 96] = p3;
    };
    size_t rb = (size_t)(((b << 3) + h) * 128 + i) * 128;
    softmax_store(xv[0], xv[1], xv[2], xv[3], (size_t)AV_OFF + rb);
    softmax_store(xr[0], xr[1], xr[2], xr[3], (size_t)AR_OFF + rb);
}

// ---------------- launch ----------------
extern "C" void kernel_launch(void* const* d_in, const int* in_sizes, int n_in,
                              void* d_out, int out_size) {
    const float* inp     = (const float*)d_in[0];
    const float* relin   = (const float*)d_in[1];
    const unsigned char* mask = (const unsigned char*)d_in[2];
    const int*   adj     = (const int*)d_in[3];
    const float* W_value = (const float*)d_in[7];
    const float* W_rel   = (const float*)d_in[8];
    const float* w_src   = (const float*)d_in[9];
    const float* w_tgt   = (const float*)d_in[10];
    const float* w_rel   = (const float*)d_in[11];
    const float* W_final = (const float*)d_in[12];
    const float* b_final = (const float*)d_in[13];
    float* out = (float*)d_out;

    k_wr<<<512, 256>>>(W_rel, w_rel);
    k_gemm<1><<<dim3(8, 16), 256>>>(inp, W_value, nullptr, 512,
                                    nullptr, nullptr, w_src, w_tgt);
    k_big<<<1024, 256>>>(relin, adj, mask, out);
    k_gemm<3><<<256, 256>>>(nullptr, nullptr, out, 128,
                            nullptr, nullptr, nullptr, nullptr);
    k_gemm<2><<<dim3(8, 16), 256>>>(nullptr, W_final, out, 1024,
                                    b_final, inp, nullptr, nullptr);
}